// round 1
// baseline (speedup 1.0000x reference)
#include <cuda_runtime.h>

// ---------------------------------------------------------------------------
// Problem constants
// ---------------------------------------------------------------------------
#define Bb  2
#define Ss  2048
#define Dd  2048
#define Hh  16
#define HDd 128
#define Ff  8192
#define LCc 512
#define EPSf 1e-6f

// ---------------------------------------------------------------------------
// Scratch (allocation-free rule: __device__ globals)
// ---------------------------------------------------------------------------
__device__ float g_em [Bb * 6 * Dd];                       // modulation + e
__device__ float g_tx [(size_t)Bb * Ss * Dd];              // 32 MB
__device__ float g_q  [(size_t)Bb * Ss * Dd];              // 32 MB
__device__ float g_k  [(size_t)Bb * Ss * Dd];              // 32 MB
__device__ float g_v  [(size_t)Bb * Ss * Dd];              // 32 MB
__device__ float g_y  [(size_t)Bb * Ss * Dd];              // 32 MB
__device__ float g_ffn[(size_t)Bb * Ss * Ff];              // 128 MB
__device__ float g_sc [(size_t)Bb * Hh * Ss * Ss];         // 512 MB (scores)

// ---------------------------------------------------------------------------
// Generic batched SGEMM: C = A @ B (+bias) (+gelu)
//   A: M x K, row-major, leading dim lda
//   B: if !TRANSB: K x N (ldb); if TRANSB: N x K (ldb) -> C = A @ B^T
//   batch index z -> (zb = z / Hdiv, zh = z % Hdiv), pointer offsets via strides.
//   All of M, N multiples of 128; K multiple of 8 (true for every call here).
// ---------------------------------------------------------------------------
__device__ __forceinline__ float gelu_t(float x) {
    float x3 = x * x * x;
    return 0.5f * x * (1.f + tanhf(0.7978845608028654f * (x + 0.044715f * x3)));
}

template <bool TRANSB, bool GELU>
__global__ __launch_bounds__(256, 2)
void sgemm_k(const float* __restrict__ A, const float* __restrict__ Bm,
             float* __restrict__ C, const float* __restrict__ bias,
             int M, int N, int K, int lda, int ldb, int ldc,
             long long sAb, long long sAh, long long sBb, long long sBh,
             long long sCb, long long sCh, int Hdiv)
{
    const int z  = blockIdx.z;
    const int zb = z / Hdiv;
    const int zh = z - zb * Hdiv;
    A  += zb * sAb + zh * sAh;
    Bm += zb * sBb + zh * sBh;
    C  += zb * sCb + zh * sCh;

    __shared__ __align__(16) float As[8][132];
    __shared__ __align__(16) float Bs[8][132];

    const int tid  = threadIdx.x;
    const int row0 = blockIdx.y * 128;
    const int col0 = blockIdx.x * 128;
    const int tx   = tid & 15;   // 0..15 -> 8 cols each
    const int ty   = tid >> 4;   // 0..15 -> 8 rows each

    float acc[8][8];
#pragma unroll
    for (int i = 0; i < 8; i++)
#pragma unroll
        for (int j = 0; j < 8; j++) acc[i][j] = 0.f;

    // load mappings
    const int ar = tid >> 1;          // 0..127
    const int ac = (tid & 1) * 4;     // 0 or 4
    const int br = tid >> 5;          // 0..7
    const int bc = (tid & 31) * 4;    // 0..124

    const float* Ap = A + (long long)(row0 + ar) * lda + ac;

    for (int k0 = 0; k0 < K; k0 += 8) {
        // A tile (always "row-major, K inner"): store transposed As[k][m]
        float4 av = *(const float4*)(Ap + k0);
        As[ac + 0][ar] = av.x;
        As[ac + 1][ar] = av.y;
        As[ac + 2][ar] = av.z;
        As[ac + 3][ar] = av.w;

        if (TRANSB) {
            // B is N x K; need Bs[k][n]
            const float* Bp = Bm + (long long)(col0 + ar) * ldb + k0 + ac;
            float4 bv = *(const float4*)Bp;
            Bs[ac + 0][ar] = bv.x;
            Bs[ac + 1][ar] = bv.y;
            Bs[ac + 2][ar] = bv.z;
            Bs[ac + 3][ar] = bv.w;
        } else {
            // B is K x N; Bs[k][n] contiguous along n
            const float* Bp = Bm + (long long)(k0 + br) * ldb + col0 + bc;
            *(float4*)&Bs[br][bc] = *(const float4*)Bp;
        }
        __syncthreads();

#pragma unroll
        for (int kk = 0; kk < 8; kk++) {
            float a[8], b[8];
            *(float4*)&a[0] = *(float4*)&As[kk][ty * 8];
            *(float4*)&a[4] = *(float4*)&As[kk][ty * 8 + 4];
            *(float4*)&b[0] = *(float4*)&Bs[kk][tx * 8];
            *(float4*)&b[4] = *(float4*)&Bs[kk][tx * 8 + 4];
#pragma unroll
            for (int i = 0; i < 8; i++)
#pragma unroll
                for (int j = 0; j < 8; j++)
                    acc[i][j] = fmaf(a[i], b[j], acc[i][j]);
        }
        __syncthreads();
    }

    // epilogue
    float bv[8];
    if (bias != nullptr) {
#pragma unroll
        for (int j = 0; j < 8; j++) bv[j] = bias[col0 + tx * 8 + j];
    } else {
#pragma unroll
        for (int j = 0; j < 8; j++) bv[j] = 0.f;
    }
#pragma unroll
    for (int i = 0; i < 8; i++) {
        float o[8];
#pragma unroll
        for (int j = 0; j < 8; j++) {
            float v = acc[i][j] + bv[j];
            if (GELU) v = gelu_t(v);
            o[j] = v;
        }
        float* Cp = C + (long long)(row0 + ty * 8 + i) * ldc + col0 + tx * 8;
        *(float4*)Cp       = make_float4(o[0], o[1], o[2], o[3]);
        *(float4*)(Cp + 4) = make_float4(o[4], o[5], o[6], o[7]);
    }
}

// ---------------------------------------------------------------------------
// Elementwise / normalization kernels
// ---------------------------------------------------------------------------
__global__ void k_copy(const float* __restrict__ a, float* __restrict__ o, long long n) {
    long long i = (long long)blockIdx.x * 256 + threadIdx.x;
    if (i < n) o[i] = a[i];
}

__global__ void k_emadd(const float* __restrict__ e, const float* __restrict__ mod,
                        float* __restrict__ em) {
    int i = blockIdx.x * 256 + threadIdx.x;
    if (i < Bb * 6 * Dd) em[i] = e[i] + mod[i % (6 * Dd)];
}

// out_row = LayerNorm(x_row) * (1 + em[b, scaleRow, :]) + em[b, shiftRow, :]
__global__ void k_ln_mod(const float* __restrict__ x, const float* __restrict__ em,
                         float* __restrict__ out, int scaleRow, int shiftRow) {
    int row = blockIdx.x;            // B*S rows
    int b   = row / Ss;
    const float* xr = x + (long long)row * Dd;
    float* orow     = out + (long long)row * Dd;
    const float* es = em + ((long long)b * 6 + scaleRow) * Dd;
    const float* eh = em + ((long long)b * 6 + shiftRow) * Dd;
    int t = threadIdx.x;             // 256 threads, 8 elems each
    float v[8];
    float s = 0.f, s2 = 0.f;
#pragma unroll
    for (int i = 0; i < 8; i++) {
        float u = xr[t + 256 * i];
        v[i] = u; s += u; s2 += u * u;
    }
    __shared__ float sh[512];
    sh[t] = s; sh[256 + t] = s2;
    __syncthreads();
    for (int o = 128; o > 0; o >>= 1) {
        if (t < o) { sh[t] += sh[t + o]; sh[256 + t] += sh[256 + t + o]; }
        __syncthreads();
    }
    float m   = sh[0] * (1.f / Dd);
    float var = sh[256] * (1.f / Dd) - m * m;
    float r   = rsqrtf(var + EPSf);
#pragma unroll
    for (int i = 0; i < 8; i++) {
        int d = t + 256 * i;
        orow[d] = (v[i] - m) * r * (1.f + es[d]) + eh[d];
    }
}

// x_row = x_row * rsqrt(mean(x^2)+eps) * w      (in place)
__global__ void k_rmsnorm(float* __restrict__ x, const float* __restrict__ w) {
    int row = blockIdx.x;
    float* xr = x + (long long)row * Dd;
    int t = threadIdx.x;
    float v[8];
    float s2 = 0.f;
#pragma unroll
    for (int i = 0; i < 8; i++) {
        float u = xr[t + 256 * i];
        v[i] = u; s2 += u * u;
    }
    __shared__ float sh[256];
    sh[t] = s2;
    __syncthreads();
    for (int o = 128; o > 0; o >>= 1) {
        if (t < o) sh[t] += sh[t + o];
        __syncthreads();
    }
    float r = rsqrtf(sh[0] * (1.f / Dd) + EPSf);
#pragma unroll
    for (int i = 0; i < 8; i++) {
        int d = t + 256 * i;
        xr[d] = v[i] * r * w[d];
    }
}

// In-place RoPE on (B,S,H,HD): pairs (2*d2, 2*d2+1), angle = freqs[s, d2]
__global__ void k_rope(float* __restrict__ q, const float* __restrict__ freqs) {
    long long i = (long long)blockIdx.x * 256 + threadIdx.x;
    const long long n = (long long)Bb * Ss * Hh * 64;
    if (i >= n) return;
    int d2 = (int)(i & 63);
    long long r  = i >> 6;           // (b*S + s)*H + h
    long long bs = r >> 4;           // H = 16
    int sIdx = (int)(bs % Ss);
    float sn, cs;
    __sincosf(freqs[sIdx * 64 + d2], &sn, &cs);
    long long base = r * HDd + 2 * d2;
    float xr = q[base], xi = q[base + 1];
    q[base]     = xr * cs - xi * sn;
    q[base + 1] = xr * sn + xi * cs;
}

// rowwise softmax of (scores * scale), in place
__global__ void k_softmax(float* __restrict__ S, int ncols, float scale) {
    long long row = blockIdx.x;
    float* p = S + row * (long long)ncols;
    int t = threadIdx.x;
    __shared__ float sh[256];
    float lm = -3.4e38f;
    for (int c = t; c < ncols; c += 256) lm = fmaxf(lm, p[c]);
    sh[t] = lm; __syncthreads();
    for (int o = 128; o > 0; o >>= 1) { if (t < o) sh[t] = fmaxf(sh[t], sh[t + o]); __syncthreads(); }
    float m = sh[0] * scale;
    __syncthreads();
    float ls = 0.f;
    for (int c = t; c < ncols; c += 256) {
        float e = __expf(p[c] * scale - m);
        p[c] = e; ls += e;
    }
    sh[t] = ls; __syncthreads();
    for (int o = 128; o > 0; o >>= 1) { if (t < o) sh[t] += sh[t + o]; __syncthreads(); }
    float inv = 1.f / sh[0];
    for (int c = t; c < ncols; c += 256) p[c] *= inv;
}

// x += y * em[b, gateRow, d]   (gateRow < 0: plain add)
__global__ void k_residual(float* __restrict__ x, const float* __restrict__ y,
                           const float* __restrict__ em, int gateRow) {
    long long i = (long long)blockIdx.x * 256 + threadIdx.x;
    const long long n = (long long)Bb * Ss * Dd;
    if (i >= n) return;
    if (gateRow >= 0) {
        int d = (int)(i % Dd);
        long long b = i / ((long long)Ss * Dd);
        x[i] += y[i] * em[(b * 6 + gateRow) * Dd + d];
    } else {
        x[i] += y[i];
    }
}

// ---------------------------------------------------------------------------
// Host orchestration
// ---------------------------------------------------------------------------
static inline void launch_gemm(const float* A, const float* Bm, float* C, const float* bias,
                               int M, int N, int K, int lda, int ldb, int ldc,
                               int batch, int Hdiv,
                               long long sAb, long long sAh, long long sBb, long long sBh,
                               long long sCb, long long sCh,
                               bool transb, bool gelu)
{
    dim3 g(N / 128, M / 128, batch), bl(256);
    if (transb)
        sgemm_k<true, false><<<g, bl>>>(A, Bm, C, bias, M, N, K, lda, ldb, ldc,
                                        sAb, sAh, sBb, sBh, sCb, sCh, Hdiv);
    else if (gelu)
        sgemm_k<false, true><<<g, bl>>>(A, Bm, C, bias, M, N, K, lda, ldb, ldc,
                                        sAb, sAh, sBb, sBh, sCb, sCh, Hdiv);
    else
        sgemm_k<false, false><<<g, bl>>>(A, Bm, C, bias, M, N, K, lda, ldb, ldc,
                                         sAb, sAh, sBb, sBh, sCb, sCh, Hdiv);
}

extern "C" void kernel_launch(void* const* d_in, const int* in_sizes, int n_in,
                              void* d_out, int out_size)
{
    // ---- input index mapping (detect dict order vs reference-signature order)
    // signature order: ... so_b(12), snq(13)=2048 elems, snk(14), cq_w(15)...
    // dict order:      ... so_b(12), cq_w(13)=D*D elems, ...
    bool sig = (in_sizes[13] == Dd);
    int I_snq, I_snk, I_cq_w, I_cq_b, I_ck_w, I_ck_b, I_cv_w, I_cv_b;
    int I_co_w, I_co_b, I_cnq, I_cnk, I_f1_w, I_f1_b, I_f2_w, I_f2_b;
    if (sig) {
        I_snq = 13; I_snk = 14;
        I_cq_w = 15; I_cq_b = 16; I_ck_w = 17; I_ck_b = 18;
        I_cv_w = 19; I_cv_b = 20; I_co_w = 21; I_co_b = 22;
        I_cnq = 23; I_cnk = 24;
        I_f1_w = 25; I_f1_b = 26; I_f2_w = 27; I_f2_b = 28;
    } else {
        I_cq_w = 13; I_cq_b = 14; I_ck_w = 15; I_ck_b = 16;
        I_cv_w = 17; I_cv_b = 18; I_co_w = 19; I_co_b = 20;
        I_f1_w = 21; I_f1_b = 22; I_f2_w = 23; I_f2_b = 24;
        I_snq = 25; I_snk = 26; I_cnq = 27; I_cnk = 28;
    }

    const float* x    = (const float*)d_in[0];
    const float* e    = (const float*)d_in[1];
    const float* ctx  = (const float*)d_in[2];
    const float* fr   = (const float*)d_in[3];
    const float* mod  = (const float*)d_in[4];
    const float* sq_w = (const float*)d_in[5];  const float* sq_b = (const float*)d_in[6];
    const float* sk_w = (const float*)d_in[7];  const float* sk_b = (const float*)d_in[8];
    const float* sv_w = (const float*)d_in[9];  const float* sv_b = (const float*)d_in[10];
    const float* so_w = (const float*)d_in[11]; const float* so_b = (const float*)d_in[12];
    const float* snq  = (const float*)d_in[I_snq];  const float* snk = (const float*)d_in[I_snk];
    const float* cq_w = (const float*)d_in[I_cq_w]; const float* cq_b = (const float*)d_in[I_cq_b];
    const float* ck_w = (const float*)d_in[I_ck_w]; const float* ck_b = (const float*)d_in[I_ck_b];
    const float* cv_w = (const float*)d_in[I_cv_w]; const float* cv_b = (const float*)d_in[I_cv_b];
    const float* co_w = (const float*)d_in[I_co_w]; const float* co_b = (const float*)d_in[I_co_b];
    const float* cnq  = (const float*)d_in[I_cnq];  const float* cnk = (const float*)d_in[I_cnk];
    const float* f1_w = (const float*)d_in[I_f1_w]; const float* f1_b = (const float*)d_in[I_f1_b];
    const float* f2_w = (const float*)d_in[I_f2_w]; const float* f2_b = (const float*)d_in[I_f2_b];

    float *em, *tx, *q, *k, *v, *y, *ffn, *sc;
    cudaGetSymbolAddress((void**)&em,  g_em);
    cudaGetSymbolAddress((void**)&tx,  g_tx);
    cudaGetSymbolAddress((void**)&q,   g_q);
    cudaGetSymbolAddress((void**)&k,   g_k);
    cudaGetSymbolAddress((void**)&v,   g_v);
    cudaGetSymbolAddress((void**)&y,   g_y);
    cudaGetSymbolAddress((void**)&ffn, g_ffn);
    cudaGetSymbolAddress((void**)&sc,  g_sc);

    float* xo = (float*)d_out;

    const long long NX = (long long)Bb * Ss * Dd;            // 8,388,608
    const float SCALE = 0.08838834764831845f;                // 1/sqrt(128)
    const long long SD = (long long)Ss * Dd;
    const long long SS = (long long)Ss * Ss;
    const long long SL = (long long)Ss * LCc;

    // x working copy into d_out
    k_copy<<<(int)((NX + 255) / 256), 256>>>(x, xo, NX);
    // em = modulation + e
    k_emadd<<<(Bb * 6 * Dd + 255) / 256, 256>>>(e, mod, em);

    // ===================== self attention =====================
    // tx = LN(x)*(1+e1)+e0
    k_ln_mod<<<Bb * Ss, 256>>>(x, em, tx, 1, 0);
    // q/k/v projections
    launch_gemm(tx, sq_w, q, sq_b, Bb * Ss, Dd, Dd, Dd, Dd, Dd, 1, 1, 0,0,0,0,0,0, false, false);
    launch_gemm(tx, sk_w, k, sk_b, Bb * Ss, Dd, Dd, Dd, Dd, Dd, 1, 1, 0,0,0,0,0,0, false, false);
    launch_gemm(tx, sv_w, v, sv_b, Bb * Ss, Dd, Dd, Dd, Dd, Dd, 1, 1, 0,0,0,0,0,0, false, false);
    k_rmsnorm<<<Bb * Ss, 256>>>(q, snq);
    k_rmsnorm<<<Bb * Ss, 256>>>(k, snk);
    // rope
    {
        long long n = (long long)Bb * Ss * Hh * 64;
        int gs = (int)((n + 255) / 256);
        k_rope<<<gs, 256>>>(q, fr);
        k_rope<<<gs, 256>>>(k, fr);
    }
    // scores[b,h] = Q[b,:,h,:] @ K[b,:,h,:]^T
    launch_gemm(q, k, sc, nullptr, Ss, Ss, HDd, Dd, Dd, Ss, Bb * Hh, Hh,
                SD, HDd, SD, HDd, (long long)Hh * SS, SS, true, false);
    k_softmax<<<Bb * Hh * Ss, 256>>>(sc, Ss, SCALE);
    // attn_out[b,:,h,:] = P[b,h] @ V[b,:,h,:]   -> tx
    launch_gemm(sc, v, tx, nullptr, Ss, HDd, Ss, Ss, Dd, Dd, Bb * Hh, Hh,
                (long long)Hh * SS, SS, SD, HDd, SD, HDd, false, false);
    // o projection + gated residual (e2)
    launch_gemm(tx, so_w, y, so_b, Bb * Ss, Dd, Dd, Dd, Dd, Dd, 1, 1, 0,0,0,0,0,0, false, false);
    k_residual<<<(int)((NX + 255) / 256), 256>>>(xo, y, em, 2);

    // ===================== cross attention =====================
    launch_gemm(xo, cq_w, q, cq_b, Bb * Ss, Dd, Dd, Dd, Dd, Dd, 1, 1, 0,0,0,0,0,0, false, false);
    k_rmsnorm<<<Bb * Ss, 256>>>(q, cnq);
    launch_gemm(ctx, ck_w, k, ck_b, Bb * LCc, Dd, Dd, Dd, Dd, Dd, 1, 1, 0,0,0,0,0,0, false, false);
    k_rmsnorm<<<Bb * LCc, 256>>>(k, cnk);
    launch_gemm(ctx, cv_w, v, cv_b, Bb * LCc, Dd, Dd, Dd, Dd, Dd, 1, 1, 0,0,0,0,0,0, false, false);
    // scores (S x LC)
    launch_gemm(q, k, sc, nullptr, Ss, LCc, HDd, Dd, Dd, LCc, Bb * Hh, Hh,
                SD, HDd, (long long)LCc * Dd, HDd, (long long)Hh * SL, SL, true, false);
    k_softmax<<<Bb * Hh * Ss, 256>>>(sc, LCc, SCALE);
    launch_gemm(sc, v, tx, nullptr, Ss, HDd, LCc, LCc, Dd, Dd, Bb * Hh, Hh,
                (long long)Hh * SL, SL, (long long)LCc * Dd, HDd, SD, HDd, false, false);
    launch_gemm(tx, co_w, y, co_b, Bb * Ss, Dd, Dd, Dd, Dd, Dd, 1, 1, 0,0,0,0,0,0, false, false);
    k_residual<<<(int)((NX + 255) / 256), 256>>>(xo, y, em, -1);

    // ===================== FFN =====================
    k_ln_mod<<<Bb * Ss, 256>>>(xo, em, tx, 4, 3);
    launch_gemm(tx, f1_w, ffn, f1_b, Bb * Ss, Ff, Dd, Dd, Ff, Ff, 1, 1, 0,0,0,0,0,0, false, true);
    launch_gemm(ffn, f2_w, y, f2_b, Bb * Ss, Dd, Ff, Ff, Dd, Dd, 1, 1, 0,0,0,0,0,0, false, false);
    k_residual<<<(int)((NX + 255) / 256), 256>>>(xo, y, em, 5);
}